// round 1
// baseline (speedup 1.0000x reference)
#include <cuda_runtime.h>

// Problem constants
#define NB 512   // batch
#define DD 512   // embed dim
#define OD 512   // out dim

// -------- scratch (no cudaMalloc allowed) --------
__device__ float g_h[NB * DD];
__device__ float g_logits[NB * DD];
__device__ float g_textw[NB * DD];
__device__ float g_outx[NB * DD];
__device__ float g_gate[NB * DD];
__device__ float g_tmp[NB * DD];

// ============================================================
// Generic 512x512x512 GEMM: C = act(A @ W + bias)
// A: [512, 512] row-major, W: [512, 512] row-major ([in, out])
// ACT: 0 = none, 1 = relu, 2 = sigmoid
// BM=BN=64, BK=16, 256 threads, 4x4 micro-tile
// ============================================================
template <int ACT>
__global__ void __launch_bounds__(256)
gemm512_kernel(const float* __restrict__ A,
               const float* __restrict__ W,
               const float* __restrict__ bias,
               float* __restrict__ C)
{
    __shared__ float As[16][64];   // [k][m]
    __shared__ float Bs[16][64];   // [k][n]

    const int m0 = blockIdx.y * 64;
    const int n0 = blockIdx.x * 64;
    const int t  = threadIdx.x;
    const int tx = t & 15;         // 16 cols of threads
    const int ty = t >> 4;         // 16 rows of threads

    float acc[4][4] = {};

    for (int k0 = 0; k0 < DD; k0 += 16) {
        // Load A tile transposed: As[k][m] = A[m0+m][k0+k]
        {
            const int m  = t >> 2;
            const int kq = (t & 3) * 4;
            float4 v = *(const float4*)&A[(size_t)(m0 + m) * DD + k0 + kq];
            As[kq + 0][m] = v.x;
            As[kq + 1][m] = v.y;
            As[kq + 2][m] = v.z;
            As[kq + 3][m] = v.w;
        }
        // Load W tile: Bs[k][n] = W[k0+k][n0+n]
        {
            const int k = t >> 4;
            const int n = (t & 15) * 4;
            *(float4*)&Bs[k][n] = *(const float4*)&W[(size_t)(k0 + k) * OD + n0 + n];
        }
        __syncthreads();

        #pragma unroll
        for (int k = 0; k < 16; k++) {
            float a[4], b[4];
            *(float4*)a = *(const float4*)&As[k][ty * 4];
            *(float4*)b = *(const float4*)&Bs[k][tx * 4];
            #pragma unroll
            for (int r = 0; r < 4; r++)
                #pragma unroll
                for (int c = 0; c < 4; c++)
                    acc[r][c] += a[r] * b[c];
        }
        __syncthreads();
    }

    #pragma unroll
    for (int r = 0; r < 4; r++) {
        const int m = m0 + ty * 4 + r;
        float4 v;
        float* vv = (float*)&v;
        #pragma unroll
        for (int c = 0; c < 4; c++) {
            const int n = n0 + tx * 4 + c;
            float x = acc[r][c] + __ldg(&bias[n]);
            if (ACT == 1) x = fmaxf(x, 0.0f);
            if (ACT == 2) x = 1.0f / (1.0f + __expf(-x));
            vv[c] = x;
        }
        *(float4*)&C[(size_t)m * OD + n0 + tx * 4] = v;
    }
}

// ============================================================
// Row softmax over 512 features, then elementwise * text.
// One block (512 threads) per row.
// ============================================================
__global__ void __launch_bounds__(512)
softmax_mul_kernel(const float* __restrict__ logits,
                   const float* __restrict__ text,
                   float* __restrict__ out)
{
    __shared__ float sdata[512];
    const int row = blockIdx.x;
    const int t   = threadIdx.x;

    const float v = logits[(size_t)row * DD + t];
    sdata[t] = v;
    __syncthreads();
    // max reduce
    for (int s = 256; s > 0; s >>= 1) {
        if (t < s) sdata[t] = fmaxf(sdata[t], sdata[t + s]);
        __syncthreads();
    }
    const float mx = sdata[0];
    __syncthreads();

    const float e = __expf(v - mx);
    sdata[t] = e;
    __syncthreads();
    // sum reduce
    for (int s = 256; s > 0; s >>= 1) {
        if (t < s) sdata[t] += sdata[t + s];
        __syncthreads();
    }
    const float inv = 1.0f / sdata[0];
    out[(size_t)row * DD + t] = e * inv * text[(size_t)row * DD + t];
}

// ============================================================
// Elementwise multiply (small-branch fallback)
// ============================================================
__global__ void mul_kernel(const float* __restrict__ a,
                           const float* __restrict__ b,
                           float* __restrict__ c, int n)
{
    int idx = blockIdx.x * blockDim.x + threadIdx.x;
    if (idx < n) c[idx] = a[idx] * b[idx];
}

// ============================================================
// Big einsum:
//   out[i, j, o] = sum_d gate[i,d] * out_x[j,d] * Wo[d,o] + bo[o]
// Block: 128(j) x 128(o) tile for a fixed i. 256 threads.
// Micro-tile 8x8 split 4+4 for conflict-free LDS.128 on B.
// A tile is out_x pre-scaled by gate[i,:] at smem-store time.
// ============================================================
__global__ void __launch_bounds__(256, 2)
big_einsum_kernel(const float* __restrict__ outx,
                  const float* __restrict__ gate,
                  const float* __restrict__ Wo,
                  const float* __restrict__ bo,
                  float* __restrict__ out)
{
    __shared__ float As[8][128];   // [k][j] = out_x[j0+j][k0+k] * gate[i][k0+k]
    __shared__ float Bs[8][128];   // [k][o] = Wo[k0+k][o0+o]
    __shared__ float gs[512];

    const int i  = blockIdx.z;
    const int j0 = blockIdx.y * 128;
    const int o0 = blockIdx.x * 128;
    const int t  = threadIdx.x;
    const int tx = t & 15;   // o-dir (16 threads)
    const int ty = t >> 4;   // j-dir (16 threads)

    // gate row into smem (covered by the loop-top barrier before first use)
    for (int k = t; k < 512; k += 256) gs[k] = gate[(size_t)i * DD + k];

    float acc[8][8] = {};

    for (int k0 = 0; k0 < DD; k0 += 8) {
        __syncthreads();   // protect prior-iter reads + gs on first iter
        // A tile (transposed, scaled by gate)
        {
            const int j  = t >> 1;              // 0..127
            const int kq = (t & 1) * 4;         // 0 or 4
            float4 v = *(const float4*)&outx[(size_t)(j0 + j) * DD + k0 + kq];
            As[kq + 0][j] = v.x * gs[k0 + kq + 0];
            As[kq + 1][j] = v.y * gs[k0 + kq + 1];
            As[kq + 2][j] = v.z * gs[k0 + kq + 2];
            As[kq + 3][j] = v.w * gs[k0 + kq + 3];
        }
        // B tile
        {
            const int k = t >> 5;               // 0..7
            const int o = (t & 31) * 4;         // 0..124
            *(float4*)&Bs[k][o] = *(const float4*)&Wo[(size_t)(k0 + k) * OD + o0 + o];
        }
        __syncthreads();

        #pragma unroll
        for (int k = 0; k < 8; k++) {
            float a[8], b[8];
            *(float4*)&a[0] = *(const float4*)&As[k][ty * 4];
            *(float4*)&a[4] = *(const float4*)&As[k][64 + ty * 4];
            *(float4*)&b[0] = *(const float4*)&Bs[k][tx * 4];
            *(float4*)&b[4] = *(const float4*)&Bs[k][64 + tx * 4];
            #pragma unroll
            for (int r = 0; r < 8; r++)
                #pragma unroll
                for (int c = 0; c < 8; c++)
                    acc[r][c] += a[r] * b[c];
        }
    }

    // Epilogue: add bias, write 512MB (store-only, coalesced 256B runs)
    float bvals[8];
    *(float4*)&bvals[0] = *(const float4*)&bo[o0 + tx * 4];
    *(float4*)&bvals[4] = *(const float4*)&bo[o0 + 64 + tx * 4];

    #pragma unroll
    for (int r = 0; r < 8; r++) {
        const int jr = (r < 4) ? (ty * 4 + r) : (64 + ty * 4 + (r - 4));
        const size_t base = (((size_t)i * NB) + (j0 + jr)) * OD + o0;
        float4 v0, v1;
        v0.x = acc[r][0] + bvals[0];
        v0.y = acc[r][1] + bvals[1];
        v0.z = acc[r][2] + bvals[2];
        v0.w = acc[r][3] + bvals[3];
        v1.x = acc[r][4] + bvals[4];
        v1.y = acc[r][5] + bvals[5];
        v1.z = acc[r][6] + bvals[6];
        v1.w = acc[r][7] + bvals[7];
        *(float4*)&out[base + tx * 4]      = v0;
        *(float4*)&out[base + 64 + tx * 4] = v1;
    }
}

// ============================================================
// kernel_launch
// Input order (metadata): image_features, text_features, cell_id,
//   Wx, bx, Wy, by, Wo, bo, Wa1, ba1, Wa2, ba2
// ============================================================
extern "C" void kernel_launch(void* const* d_in, const int* in_sizes, int n_in,
                              void* d_out, int out_size)
{
    const float* image = (const float*)d_in[0];
    const float* text  = (const float*)d_in[1];
    // d_in[2] = cell_id (int32 scalar) — branch decided by out_size (graph-safe)
    const float* Wx  = (const float*)d_in[3];
    const float* bx  = (const float*)d_in[4];
    const float* Wy  = (const float*)d_in[5];
    const float* by  = (const float*)d_in[6];
    const float* Wo  = (const float*)d_in[7];
    const float* bo  = (const float*)d_in[8];
    const float* Wa1 = (const float*)d_in[9];
    const float* ba1 = (const float*)d_in[10];
    const float* Wa2 = (const float*)d_in[11];
    const float* ba2 = (const float*)d_in[12];
    float* out = (float*)d_out;

    float *h, *logits, *textw, *outx, *gate, *tmp;
    cudaGetSymbolAddress((void**)&h,      g_h);
    cudaGetSymbolAddress((void**)&logits, g_logits);
    cudaGetSymbolAddress((void**)&textw,  g_textw);
    cudaGetSymbolAddress((void**)&outx,   g_outx);
    cudaGetSymbolAddress((void**)&gate,   g_gate);
    cudaGetSymbolAddress((void**)&tmp,    g_tmp);

    const dim3 gsmall(OD / 64, NB / 64);   // 8x8 blocks

    // Attention MLP: h = relu(text @ Wa1 + ba1)
    gemm512_kernel<1><<<gsmall, 256>>>(text, Wa1, ba1, h);
    // logits = h @ Wa2 + ba2
    gemm512_kernel<0><<<gsmall, 256>>>(h, Wa2, ba2, logits);
    // attn = softmax(logits, axis=1); textw = attn * text
    softmax_mul_kernel<<<NB, 512>>>(logits, text, textw);
    // out_x = image @ Wx + bx
    gemm512_kernel<0><<<gsmall, 256>>>(image, Wx, bx, outx);
    // gate = sigmoid(textw @ Wy + by)
    gemm512_kernel<2><<<gsmall, 256>>>(textw, Wy, by, gate);

    if (out_size == NB * NB * OD) {
        // Big branch: out[i,j,o] = sum_d gate[i,d]*out_x[j,d]*Wo[d,o] + bo[o]
        dim3 grid(OD / 128, NB / 128, NB);   // (4, 4, 512)
        big_einsum_kernel<<<grid, 256>>>(outx, gate, Wo, bo, out);
    } else {
        // Small branch fallback: out = (gate * out_x) @ Wo + bo
        mul_kernel<<<(NB * DD + 255) / 256, 256>>>(gate, outx, tmp, NB * DD);
        gemm512_kernel<0><<<gsmall, 256>>>(tmp, Wo, bo, out);
    }
}

// round 3
// speedup vs baseline: 1.8102x; 1.8102x over previous
#include <cuda_runtime.h>
#include <cuda_bf16.h>
#include <cstdint>

#define NB 512   // batch
#define DD 512   // embed dim
#define OD 512   // out dim

// -------- scratch (no cudaMalloc allowed) --------
__device__ float g_h[NB * DD];
__device__ float g_logits[NB * DD];
__device__ float g_textw[NB * DD];
__device__ float g_outx[NB * DD];
__device__ float g_gate[NB * DD];
__device__ float g_tmp[NB * DD];
__device__ __nv_bfloat16 g_WoTh[OD * DD];   // WoT_hi[o][d]
__device__ __nv_bfloat16 g_WoTl[OD * DD];   // WoT_lo[o][d]

// ============================================================
// Helpers (plain sm_80+ PTX only: mma.sync / ldmatrix / cp.async)
// ============================================================
__device__ __forceinline__ uint32_t smem_u32(const void* p) {
    uint32_t a;
    asm("{ .reg .u64 t; cvta.to.shared.u64 t, %1; cvt.u32.u64 %0, t; }"
        : "=r"(a) : "l"(p));
    return a;
}

#define CP_ASYNC_16(dst, src) \
    asm volatile("cp.async.cg.shared.global [%0], [%1], 16;" \
                 :: "r"((uint32_t)(dst)), "l"(src))
#define CP_ASYNC_COMMIT() asm volatile("cp.async.commit_group;" ::: "memory")
#define CP_ASYNC_WAIT0()  asm volatile("cp.async.wait_group 0;" ::: "memory")

__device__ __forceinline__ void ldsm_x4(uint32_t r[4], uint32_t addr) {
    asm volatile("ldmatrix.sync.aligned.m8n8.x4.shared.b16 {%0,%1,%2,%3}, [%4];"
                 : "=r"(r[0]), "=r"(r[1]), "=r"(r[2]), "=r"(r[3]) : "r"(addr));
}

__device__ __forceinline__ void mma_bf16(float c[4], const uint32_t a[4],
                                         const uint32_t b0, const uint32_t b1) {
    asm volatile(
        "mma.sync.aligned.m16n8k16.row.col.f32.bf16.bf16.f32 "
        "{%0,%1,%2,%3}, {%4,%5,%6,%7}, {%8,%9}, {%0,%1,%2,%3};"
        : "+f"(c[0]), "+f"(c[1]), "+f"(c[2]), "+f"(c[3])
        : "r"(a[0]), "r"(a[1]), "r"(a[2]), "r"(a[3]), "r"(b0), "r"(b1));
}

// ============================================================
// smem layout for big kernel (dynamic)
//   gate row: 2048 B
//   2 buffers, each: AH(10240) AL(10240) BH(10240) BL(10240) = 40960 B
//   rows are 128 x (40 bf16) = stride 80 B  (conflict-free for ldmatrix)
// ============================================================
#define ASTRIDE 80
#define BUF_BYTES 40960
#define OFF_AH 0
#define OFF_AL 10240
#define OFF_BH 20480
#define OFF_BL 30720
#define SMEM_BYTES (2048 + 2 * BUF_BYTES)   // 83968

// ============================================================
// Preamble: generic 512x512x512 fp32 GEMM: C = act(A @ W + bias)
// ============================================================
template <int ACT>
__global__ void __launch_bounds__(256)
gemm512_kernel(const float* __restrict__ A, const float* __restrict__ W,
               const float* __restrict__ bias, float* __restrict__ C)
{
    __shared__ float As[16][64];
    __shared__ float Bs[16][64];
    const int m0 = blockIdx.y * 64, n0 = blockIdx.x * 64;
    const int t = threadIdx.x, tx = t & 15, ty = t >> 4;
    float acc[4][4] = {};
    for (int k0 = 0; k0 < DD; k0 += 16) {
        {
            const int m = t >> 2, kq = (t & 3) * 4;
            float4 v = *(const float4*)&A[(size_t)(m0 + m) * DD + k0 + kq];
            As[kq + 0][m] = v.x; As[kq + 1][m] = v.y;
            As[kq + 2][m] = v.z; As[kq + 3][m] = v.w;
        }
        {
            const int k = t >> 4, n = (t & 15) * 4;
            *(float4*)&Bs[k][n] = *(const float4*)&W[(size_t)(k0 + k) * OD + n0 + n];
        }
        __syncthreads();
        #pragma unroll
        for (int k = 0; k < 16; k++) {
            float a[4], b[4];
            *(float4*)a = *(const float4*)&As[k][ty * 4];
            *(float4*)b = *(const float4*)&Bs[k][tx * 4];
            #pragma unroll
            for (int r = 0; r < 4; r++)
                #pragma unroll
                for (int c = 0; c < 4; c++)
                    acc[r][c] += a[r] * b[c];
        }
        __syncthreads();
    }
    #pragma unroll
    for (int r = 0; r < 4; r++) {
        const int m = m0 + ty * 4 + r;
        float4 v; float* vv = (float*)&v;
        #pragma unroll
        for (int c = 0; c < 4; c++) {
            float x = acc[r][c] + __ldg(&bias[n0 + tx * 4 + c]);
            if (ACT == 1) x = fmaxf(x, 0.0f);
            if (ACT == 2) x = 1.0f / (1.0f + __expf(-x));
            vv[c] = x;
        }
        *(float4*)&C[(size_t)m * OD + n0 + tx * 4] = v;
    }
}

// ============================================================
// Preamble: row softmax * text
// ============================================================
__global__ void __launch_bounds__(512)
softmax_mul_kernel(const float* __restrict__ logits, const float* __restrict__ text,
                   float* __restrict__ out)
{
    __shared__ float sdata[512];
    const int row = blockIdx.x, t = threadIdx.x;
    const float v = logits[(size_t)row * DD + t];
    sdata[t] = v; __syncthreads();
    for (int s = 256; s > 0; s >>= 1) { if (t < s) sdata[t] = fmaxf(sdata[t], sdata[t + s]); __syncthreads(); }
    const float mx = sdata[0]; __syncthreads();
    const float e = __expf(v - mx);
    sdata[t] = e; __syncthreads();
    for (int s = 256; s > 0; s >>= 1) { if (t < s) sdata[t] += sdata[t + s]; __syncthreads(); }
    out[(size_t)row * DD + t] = e * (1.0f / sdata[0]) * text[(size_t)row * DD + t];
}

// ============================================================
// Preamble: transpose + bf16 hi/lo split of Wo
// ============================================================
__global__ void __launch_bounds__(256)
split_transpose_wo(const float* __restrict__ Wo,
                   __nv_bfloat16* __restrict__ Th, __nv_bfloat16* __restrict__ Tl)
{
    __shared__ float tile[32][33];
    const int bo = blockIdx.x * 32;
    const int bd = blockIdx.y * 32;
    const int x = threadIdx.x, y = threadIdx.y;   // (32, 8)
    #pragma unroll
    for (int r = 0; r < 4; r++)
        tile[y + 8 * r][x] = Wo[(size_t)(bd + y + 8 * r) * OD + bo + x];
    __syncthreads();
    #pragma unroll
    for (int r = 0; r < 4; r++) {
        const int o = bo + y + 8 * r;
        const int d = bd + x;
        const float v = tile[x][y + 8 * r];
        const __nv_bfloat16 h = __float2bfloat16_rn(v);
        const float lo = v - __bfloat162float(h);
        Th[(size_t)o * DD + d] = h;
        Tl[(size_t)o * DD + d] = __float2bfloat16_rn(lo);
    }
}

__global__ void mul_kernel(const float* __restrict__ a, const float* __restrict__ b,
                           float* __restrict__ c, int n)
{
    int idx = blockIdx.x * blockDim.x + threadIdx.x;
    if (idx < n) c[idx] = a[idx] * b[idx];
}

// ============================================================
// Big einsum via HMMA bf16x3:
//   out[i,j,o] = sum_d gate[i,d]*outx[j,d]*Wo[d,o] + bo[o]
// grid (4 o-tiles, 4 j-tiles, 512 i), 256 threads.
// CTA tile 128(j) x 128(o); warp tile 32x64; K chunks of 32, double-buffered.
// 3 passes: Ah*Bh, Ah*Bl, Al*Bh (fp32 accum) -> ~eps^2 error.
// ============================================================
__global__ void __launch_bounds__(256, 2)
big_einsum_hmma_kernel(const float* __restrict__ outx, const float* __restrict__ gate,
                       const float* __restrict__ bo, float* __restrict__ out)
{
    extern __shared__ char dynsmem[];
    float* gs = (float*)dynsmem;
    const uint32_t sbase = smem_u32(dynsmem) + 2048u;   // buffers base

    const int i  = blockIdx.z;
    const int j0 = blockIdx.y * 128;
    const int o0 = blockIdx.x * 128;
    const int tid  = threadIdx.x;
    const int wid  = tid >> 5;
    const int lane = tid & 31;
    const int warp_m = wid & 3;     // j dir: 4 warps x 32 rows
    const int warp_n = wid >> 2;    // o dir: 2 warps x 64 cols

    // ---- gate row -> smem ----
    gs[tid]       = gate[(size_t)i * DD + tid];
    gs[tid + 256] = gate[(size_t)i * DD + tid + 256];

    // ---- A-build indices (per thread: one row-half of 16 cols) ----
    const int arow = tid >> 1;
    const int ach  = (tid & 1) * 16;

    // ---- cp.async B helper: chunk c -> buffer buf ----
    auto cpB = [&](int c, int buf) {
        const int c0 = c * 32;
        const uint32_t bh = sbase + buf * BUF_BYTES + OFF_BH;
        const uint32_t bl = sbase + buf * BUF_BYTES + OFF_BL;
        #pragma unroll
        for (int q = 0; q < 2; q++) {
            const int g   = tid + q * 256;      // granule 0..511
            const int row = g >> 2;             // 0..127
            const int ck  = g & 3;              // 16B chunk within 64B row
            const uint32_t dso = (uint32_t)(row * ASTRIDE + ck * 16);
            const __nv_bfloat16* sh = g_WoTh + (size_t)(o0 + row) * DD + c0 + ck * 8;
            const __nv_bfloat16* sl = g_WoTl + (size_t)(o0 + row) * DD + c0 + ck * 8;
            CP_ASYNC_16(bh + dso, sh);
            CP_ASYNC_16(bl + dso, sl);
        }
        CP_ASYNC_COMMIT();
    };

    // ---- A load (registers) ----
    float4 av[4];
    auto loadA = [&](int c) {
        const float* p = outx + (size_t)(j0 + arow) * DD + c * 32 + ach;
        #pragma unroll
        for (int q = 0; q < 4; q++) av[q] = __ldg((const float4*)(p + q * 4));
    };

    // ---- A convert + store ----
    auto storeA = [&](int c, int buf) {
        const int c0 = c * 32;
        uint32_t hi[8], lo[8];
        #pragma unroll
        for (int q = 0; q < 4; q++) {
            const float4 g4 = *(const float4*)&gs[c0 + ach + q * 4];
            float x0 = av[q].x * g4.x, x1 = av[q].y * g4.y;
            float x2 = av[q].z * g4.z, x3 = av[q].w * g4.w;
            __nv_bfloat16 h0 = __float2bfloat16_rn(x0);
            __nv_bfloat16 h1 = __float2bfloat16_rn(x1);
            __nv_bfloat16 h2 = __float2bfloat16_rn(x2);
            __nv_bfloat16 h3 = __float2bfloat16_rn(x3);
            __nv_bfloat16 l0 = __float2bfloat16_rn(x0 - __bfloat162float(h0));
            __nv_bfloat16 l1 = __float2bfloat16_rn(x1 - __bfloat162float(h1));
            __nv_bfloat16 l2 = __float2bfloat16_rn(x2 - __bfloat162float(h2));
            __nv_bfloat16 l3 = __float2bfloat16_rn(x3 - __bfloat162float(h3));
            __nv_bfloat162 ph0 = {h0, h1}, ph1 = {h2, h3};
            __nv_bfloat162 pl0 = {l0, l1}, pl1 = {l2, l3};
            hi[q * 2] = *(uint32_t*)&ph0; hi[q * 2 + 1] = *(uint32_t*)&ph1;
            lo[q * 2] = *(uint32_t*)&pl0; lo[q * 2 + 1] = *(uint32_t*)&pl1;
        }
        const uint32_t ah = sbase + buf * BUF_BYTES + OFF_AH + arow * ASTRIDE + ach * 2;
        const uint32_t al = sbase + buf * BUF_BYTES + OFF_AL + arow * ASTRIDE + ach * 2;
        asm volatile("st.shared.v4.b32 [%0], {%1,%2,%3,%4};" :: "r"(ah), "r"(hi[0]), "r"(hi[1]), "r"(hi[2]), "r"(hi[3]));
        asm volatile("st.shared.v4.b32 [%0], {%1,%2,%3,%4};" :: "r"(ah + 16), "r"(hi[4]), "r"(hi[5]), "r"(hi[6]), "r"(hi[7]));
        asm volatile("st.shared.v4.b32 [%0], {%1,%2,%3,%4};" :: "r"(al), "r"(lo[0]), "r"(lo[1]), "r"(lo[2]), "r"(lo[3]));
        asm volatile("st.shared.v4.b32 [%0], {%1,%2,%3,%4};" :: "r"(al + 16), "r"(lo[4]), "r"(lo[5]), "r"(lo[6]), "r"(lo[7]));
    };

    // ---- lane offsets for ldmatrix (bytes) ----
    // A tiles: t = lane>>3: {rows+0/k0, rows+8/k0, rows+0/k8, rows+8/k8}
    const uint32_t a_lane = (uint32_t)(((lane & 7) + ((lane >> 3) & 1) * 8) * ASTRIDE
                                       + (lane >> 4) * 16);
    // B tiles: t: {n+0/k0, n+0/k8, n+8/k0, n+8/k8}
    const uint32_t b_lane = (uint32_t)(((lane & 7) + (lane >> 4) * 8) * ASTRIDE
                                       + ((lane >> 3) & 1) * 16);
    const uint32_t a_warp = (uint32_t)(warp_m * 32 * ASTRIDE);
    const uint32_t b_warp = (uint32_t)(warp_n * 64 * ASTRIDE);

    float acc[2][8][4] = {};

    // ---- prologue: stage chunk 0 ----
    loadA(0);
    cpB(0, 0);
    __syncthreads();          // gs visible for storeA
    storeA(0, 0);
    CP_ASYNC_WAIT0();
    __syncthreads();          // buffer 0 ready

    // ---- main loop over 16 K-chunks ----
    for (int c = 0; c < 16; c++) {
        const int buf = c & 1;
        if (c < 15) { loadA(c + 1); cpB(c + 1, buf ^ 1); }

        const uint32_t bb = sbase + buf * BUF_BYTES;
        // 3 passes: (AH,BH), (AH,BL), (AL,BH)
        #pragma unroll
        for (int p = 0; p < 3; p++) {
            const uint32_t abase = bb + ((p == 2) ? OFF_AL : OFF_AH) + a_warp + a_lane;
            const uint32_t bbase = bb + ((p == 1) ? OFF_BL : OFF_BH) + b_warp + b_lane;
            #pragma unroll
            for (int ks = 0; ks < 2; ks++) {
                uint32_t afrag[2][4];
                ldsm_x4(afrag[0], abase + ks * 32);
                ldsm_x4(afrag[1], abase + 16 * ASTRIDE + ks * 32);
                #pragma unroll
                for (int g = 0; g < 4; g++) {
                    uint32_t bfrag[4];
                    ldsm_x4(bfrag, bbase + g * 16 * ASTRIDE + ks * 32);
                    mma_bf16(acc[0][g * 2],     afrag[0], bfrag[0], bfrag[1]);
                    mma_bf16(acc[1][g * 2],     afrag[1], bfrag[0], bfrag[1]);
                    mma_bf16(acc[0][g * 2 + 1], afrag[0], bfrag[2], bfrag[3]);
                    mma_bf16(acc[1][g * 2 + 1], afrag[1], bfrag[2], bfrag[3]);
                }
            }
        }

        if (c < 15) {
            storeA(c + 1, buf ^ 1);
            CP_ASYNC_WAIT0();
            __syncthreads();
        }
    }

    // ---- epilogue: bias + store ----
    const int colb = o0 + warp_n * 64 + (lane & 3) * 2;
    float2 bv[8];
    #pragma unroll
    for (int nj = 0; nj < 8; nj++)
        bv[nj] = __ldg((const float2*)&bo[colb + nj * 8]);

    const int rowb = j0 + warp_m * 32 + (lane >> 2);
    #pragma unroll
    for (int mi = 0; mi < 2; mi++) {
        #pragma unroll
        for (int h = 0; h < 2; h++) {
            const size_t rbase = ((size_t)i * NB + (rowb + mi * 16 + h * 8)) * OD;
            #pragma unroll
            for (int nj = 0; nj < 8; nj++) {
                float2 v;
                v.x = acc[mi][nj][h * 2]     + bv[nj].x;
                v.y = acc[mi][nj][h * 2 + 1] + bv[nj].y;
                *(float2*)&out[rbase + colb + nj * 8] = v;
            }
        }
    }
}

// ============================================================
// kernel_launch
// ============================================================
extern "C" void kernel_launch(void* const* d_in, const int* in_sizes, int n_in,
                              void* d_out, int out_size)
{
    const float* image = (const float*)d_in[0];
    const float* text  = (const float*)d_in[1];
    const float* Wx  = (const float*)d_in[3];
    const float* bx  = (const float*)d_in[4];
    const float* Wy  = (const float*)d_in[5];
    const float* by  = (const float*)d_in[6];
    const float* Wo  = (const float*)d_in[7];
    const float* bo  = (const float*)d_in[8];
    const float* Wa1 = (const float*)d_in[9];
    const float* ba1 = (const float*)d_in[10];
    const float* Wa2 = (const float*)d_in[11];
    const float* ba2 = (const float*)d_in[12];
    float* out = (float*)d_out;

    float *h, *logits, *textw, *outx, *gate, *tmp;
    __nv_bfloat16 *woth, *wotl;
    cudaGetSymbolAddress((void**)&h,      g_h);
    cudaGetSymbolAddress((void**)&logits, g_logits);
    cudaGetSymbolAddress((void**)&textw,  g_textw);
    cudaGetSymbolAddress((void**)&outx,   g_outx);
    cudaGetSymbolAddress((void**)&gate,   g_gate);
    cudaGetSymbolAddress((void**)&tmp,    g_tmp);
    cudaGetSymbolAddress((void**)&woth,   g_WoTh);
    cudaGetSymbolAddress((void**)&wotl,   g_WoTl);

    cudaFuncSetAttribute(big_einsum_hmma_kernel,
                         cudaFuncAttributeMaxDynamicSharedMemorySize, SMEM_BYTES);

    const dim3 gsmall(OD / 64, NB / 64);

    // Wo transpose + bf16 hi/lo split
    split_transpose_wo<<<dim3(16, 16), dim3(32, 8)>>>(Wo, woth, wotl);
    // Attention MLP chain
    gemm512_kernel<1><<<gsmall, 256>>>(text, Wa1, ba1, h);
    gemm512_kernel<0><<<gsmall, 256>>>(h, Wa2, ba2, logits);
    softmax_mul_kernel<<<NB, 512>>>(logits, text, textw);
    gemm512_kernel<0><<<gsmall, 256>>>(image, Wx, bx, outx);
    gemm512_kernel<2><<<gsmall, 256>>>(textw, Wy, by, gate);

    if (out_size == NB * NB * OD) {
        dim3 grid(OD / 128, NB / 128, NB);   // (4 o, 4 j, 512 i)
        big_einsum_hmma_kernel<<<grid, 256, SMEM_BYTES>>>(outx, gate, bo, out);
    } else {
        mul_kernel<<<(NB * DD + 255) / 256, 256>>>(gate, outx, tmp, NB * DD);
        gemm512_kernel<0><<<gsmall, 256>>>(tmp, Wo, bo, out);
    }
}

// round 4
// speedup vs baseline: 2.1451x; 1.1850x over previous
#include <cuda_runtime.h>
#include <cuda_bf16.h>
#include <cstdint>

#define NB 512   // batch
#define DD 512   // embed dim
#define OD 512   // out dim

// -------- scratch (no cudaMalloc allowed) --------
__device__ float g_h[NB * DD];
__device__ float g_logits[NB * DD];
__device__ float g_textw[NB * DD];
__device__ float g_outx[NB * DD];
__device__ float g_gate[NB * DD];
__device__ float g_tmp[NB * DD];
__device__ __nv_bfloat16 g_WoTh[OD * DD];   // WoT_hi[o][d]
__device__ __nv_bfloat16 g_WoTl[OD * DD];   // WoT_lo[o][d]

// ============================================================
// Helpers (plain sm_80+ PTX only: mma.sync / ldmatrix / cp.async)
// ============================================================
__device__ __forceinline__ uint32_t smem_u32(const void* p) {
    uint32_t a;
    asm("{ .reg .u64 t; cvta.to.shared.u64 t, %1; cvt.u32.u64 %0, t; }"
        : "=r"(a) : "l"(p));
    return a;
}

#define CP_ASYNC_16(dst, src) \
    asm volatile("cp.async.cg.shared.global [%0], [%1], 16;" \
                 :: "r"((uint32_t)(dst)), "l"(src))
#define CP_ASYNC_COMMIT() asm volatile("cp.async.commit_group;" ::: "memory")
#define CP_ASYNC_WAIT0()  asm volatile("cp.async.wait_group 0;" ::: "memory")

__device__ __forceinline__ void ldsm_x4(uint32_t r[4], uint32_t addr) {
    asm volatile("ldmatrix.sync.aligned.m8n8.x4.shared.b16 {%0,%1,%2,%3}, [%4];"
                 : "=r"(r[0]), "=r"(r[1]), "=r"(r[2]), "=r"(r[3]) : "r"(addr));
}

__device__ __forceinline__ void mma_bf16(float c[4], const uint32_t a[4],
                                         const uint32_t b0, const uint32_t b1) {
    asm volatile(
        "mma.sync.aligned.m16n8k16.row.col.f32.bf16.bf16.f32 "
        "{%0,%1,%2,%3}, {%4,%5,%6,%7}, {%8,%9}, {%0,%1,%2,%3};"
        : "+f"(c[0]), "+f"(c[1]), "+f"(c[2]), "+f"(c[3])
        : "r"(a[0]), "r"(a[1]), "r"(a[2]), "r"(a[3]), "r"(b0), "r"(b1));
}

// ============================================================
// smem layout for big kernel (dynamic)
//   gate row: 2048 B
//   2 buffers, each: AH(10240) AL(10240) BH(20480) BL(20480) = 61440 B
//   rows: 32 bf16 data + pad, stride 80 B (conflict-free ldmatrix)
// ============================================================
#define ASTRIDE 80
#define OFF_AH 0
#define OFF_AL 10240
#define OFF_BH 20480
#define OFF_BL 40960
#define BUF_BYTES 61440
#define SMEM_BYTES (2048 + 2 * BUF_BYTES)   // 124928

// ============================================================
// Preamble small GEMM core: BM=64, BN=32, BK=16, 128 threads
// ============================================================
template <int ACT>
__device__ __forceinline__ void gemm_small_body(
    const float* __restrict__ A, const float* __restrict__ W,
    const float* __restrict__ bias, float* __restrict__ C,
    int m0, int n0)
{
    __shared__ float As[16][64];
    __shared__ float Bs[16][32];
    const int t = threadIdx.x;
    const int tx = t & 7, ty = t >> 3;
    float acc[4][4] = {};
    for (int k0 = 0; k0 < DD; k0 += 16) {
        {
            const int m = t >> 1;
            const int kq = (t & 1) * 8;
            float4 v0 = *(const float4*)&A[(size_t)(m0 + m) * DD + k0 + kq];
            float4 v1 = *(const float4*)&A[(size_t)(m0 + m) * DD + k0 + kq + 4];
            As[kq + 0][m] = v0.x; As[kq + 1][m] = v0.y;
            As[kq + 2][m] = v0.z; As[kq + 3][m] = v0.w;
            As[kq + 4][m] = v1.x; As[kq + 5][m] = v1.y;
            As[kq + 6][m] = v1.z; As[kq + 7][m] = v1.w;
        }
        {
            const int k = t >> 3, n = (t & 7) * 4;
            *(float4*)&Bs[k][n] = *(const float4*)&W[(size_t)(k0 + k) * OD + n0 + n];
        }
        __syncthreads();
        #pragma unroll
        for (int k = 0; k < 16; k++) {
            float a[4], b[4];
            *(float4*)a = *(const float4*)&As[k][ty * 4];
            *(float4*)b = *(const float4*)&Bs[k][tx * 4];
            #pragma unroll
            for (int r = 0; r < 4; r++)
                #pragma unroll
                for (int c = 0; c < 4; c++)
                    acc[r][c] += a[r] * b[c];
        }
        __syncthreads();
    }
    #pragma unroll
    for (int r = 0; r < 4; r++) {
        const int m = m0 + ty * 4 + r;
        float4 v; float* vv = (float*)&v;
        #pragma unroll
        for (int c = 0; c < 4; c++) {
            float x = acc[r][c] + __ldg(&bias[n0 + tx * 4 + c]);
            if (ACT == 1) x = fmaxf(x, 0.0f);
            if (ACT == 2) x = 1.0f / (1.0f + __expf(-x));
            vv[c] = x;
        }
        *(float4*)&C[(size_t)m * OD + n0 + tx * 4] = v;
    }
}

template <int ACT>
__global__ void __launch_bounds__(128)
gemm_small_kernel(const float* __restrict__ A, const float* __restrict__ W,
                  const float* __restrict__ bias, float* __restrict__ C)
{
    gemm_small_body<ACT>(A, W, bias, C, blockIdx.y * 64, blockIdx.x * 32);
}

// Fused first stage: z=0 -> h = relu(text@Wa1+ba1); z=1 -> outx = image@Wx+bx
__global__ void __launch_bounds__(128)
pre_fused_kernel(const float* __restrict__ text, const float* __restrict__ image,
                 const float* __restrict__ Wa1, const float* __restrict__ ba1,
                 const float* __restrict__ Wx,  const float* __restrict__ bx,
                 float* __restrict__ h, float* __restrict__ outx)
{
    if (blockIdx.z == 0)
        gemm_small_body<1>(text, Wa1, ba1, h, blockIdx.y * 64, blockIdx.x * 32);
    else
        gemm_small_body<0>(image, Wx, bx, outx, blockIdx.y * 64, blockIdx.x * 32);
}

// ============================================================
// Preamble: row softmax * text
// ============================================================
__global__ void __launch_bounds__(512)
softmax_mul_kernel(const float* __restrict__ logits, const float* __restrict__ text,
                   float* __restrict__ out)
{
    __shared__ float sdata[512];
    const int row = blockIdx.x, t = threadIdx.x;
    const float v = logits[(size_t)row * DD + t];
    sdata[t] = v; __syncthreads();
    for (int s = 256; s > 0; s >>= 1) { if (t < s) sdata[t] = fmaxf(sdata[t], sdata[t + s]); __syncthreads(); }
    const float mx = sdata[0]; __syncthreads();
    const float e = __expf(v - mx);
    sdata[t] = e; __syncthreads();
    for (int s = 256; s > 0; s >>= 1) { if (t < s) sdata[t] += sdata[t + s]; __syncthreads(); }
    out[(size_t)row * DD + t] = e * (1.0f / sdata[0]) * text[(size_t)row * DD + t];
}

// ============================================================
// Preamble: transpose + bf16 hi/lo split of Wo
// ============================================================
__global__ void __launch_bounds__(256)
split_transpose_wo(const float* __restrict__ Wo,
                   __nv_bfloat16* __restrict__ Th, __nv_bfloat16* __restrict__ Tl)
{
    __shared__ float tile[32][33];
    const int bo = blockIdx.x * 32;
    const int bd = blockIdx.y * 32;
    const int x = threadIdx.x, y = threadIdx.y;   // (32, 8)
    #pragma unroll
    for (int r = 0; r < 4; r++)
        tile[y + 8 * r][x] = Wo[(size_t)(bd + y + 8 * r) * OD + bo + x];
    __syncthreads();
    #pragma unroll
    for (int r = 0; r < 4; r++) {
        const int o = bo + y + 8 * r;
        const int d = bd + x;
        const float v = tile[x][y + 8 * r];
        const __nv_bfloat16 h = __float2bfloat16_rn(v);
        const float lo = v - __bfloat162float(h);
        Th[(size_t)o * DD + d] = h;
        Tl[(size_t)o * DD + d] = __float2bfloat16_rn(lo);
    }
}

__global__ void mul_kernel(const float* __restrict__ a, const float* __restrict__ b,
                           float* __restrict__ c, int n)
{
    int idx = blockIdx.x * blockDim.x + threadIdx.x;
    if (idx < n) c[idx] = a[idx] * b[idx];
}

// ============================================================
// Big einsum via HMMA bf16x3:
//   out[i,j,o] = sum_d gate[i,d]*outx[j,d]*Wo[d,o] + bo[o]
// grid (2 o-tiles, 4 j-tiles, 512 i) = 4096 CTAs, 256 threads.
// CTA tile 128(j) x 256(o); warp tile 64x64 (warp_m = wid&1, warp_n = wid>>1).
// K chunks of 32, double-buffered; shared-A fragments across the 3 passes.
// ============================================================
__global__ void __launch_bounds__(256, 1)
big_einsum_hmma_kernel(const float* __restrict__ outx, const float* __restrict__ gate,
                       const float* __restrict__ bo, float* __restrict__ out)
{
    extern __shared__ char dynsmem[];
    float* gs = (float*)dynsmem;
    const uint32_t sbase = smem_u32(dynsmem) + 2048u;

    const int i  = blockIdx.z;
    const int j0 = blockIdx.y * 128;
    const int o0 = blockIdx.x * 256;
    const int tid  = threadIdx.x;
    const int wid  = tid >> 5;
    const int lane = tid & 31;
    const int warp_m = wid & 1;     // 2 x 64 rows (j)
    const int warp_n = wid >> 1;    // 4 x 64 cols (o)

    // ---- gate row -> smem ----
    gs[tid]       = gate[(size_t)i * DD + tid];
    gs[tid + 256] = gate[(size_t)i * DD + tid + 256];

    // ---- A-build indices: row = tid>>1, 16-col half ----
    const int arow = tid >> 1;
    const int ach  = (tid & 1) * 16;

    // ---- cp.async B (hi+lo): 256 rows x 64B each ----
    auto cpB = [&](int c, int buf) {
        const int c0 = c * 32;
        const uint32_t bh = sbase + buf * BUF_BYTES + OFF_BH;
        const uint32_t bl = sbase + buf * BUF_BYTES + OFF_BL;
        #pragma unroll
        for (int q = 0; q < 4; q++) {
            const int g   = tid + q * 256;      // 0..1023
            const int row = g >> 2;             // 0..255
            const int ck  = g & 3;
            const uint32_t dso = (uint32_t)(row * ASTRIDE + ck * 16);
            const __nv_bfloat16* sh = g_WoTh + (size_t)(o0 + row) * DD + c0 + ck * 8;
            const __nv_bfloat16* sl = g_WoTl + (size_t)(o0 + row) * DD + c0 + ck * 8;
            CP_ASYNC_16(bh + dso, sh);
            CP_ASYNC_16(bl + dso, sl);
        }
        CP_ASYNC_COMMIT();
    };

    // ---- A gmem load (registers) ----
    float4 av[4];
    auto loadA = [&](int c) {
        const float* p = outx + (size_t)(j0 + arow) * DD + c * 32 + ach;
        #pragma unroll
        for (int q = 0; q < 4; q++) av[q] = __ldg((const float4*)(p + q * 4));
    };

    // ---- A convert (gate-scaled) + hi/lo split + store ----
    auto storeA = [&](int c, int buf) {
        const int c0 = c * 32;
        uint32_t hi[8], lo[8];
        #pragma unroll
        for (int q = 0; q < 4; q++) {
            const float4 g4 = *(const float4*)&gs[c0 + ach + q * 4];
            float x0 = av[q].x * g4.x, x1 = av[q].y * g4.y;
            float x2 = av[q].z * g4.z, x3 = av[q].w * g4.w;
            __nv_bfloat16 h0 = __float2bfloat16_rn(x0);
            __nv_bfloat16 h1 = __float2bfloat16_rn(x1);
            __nv_bfloat16 h2 = __float2bfloat16_rn(x2);
            __nv_bfloat16 h3 = __float2bfloat16_rn(x3);
            __nv_bfloat16 l0 = __float2bfloat16_rn(x0 - __bfloat162float(h0));
            __nv_bfloat16 l1 = __float2bfloat16_rn(x1 - __bfloat162float(h1));
            __nv_bfloat16 l2 = __float2bfloat16_rn(x2 - __bfloat162float(h2));
            __nv_bfloat16 l3 = __float2bfloat16_rn(x3 - __bfloat162float(h3));
            __nv_bfloat162 ph0 = {h0, h1}, ph1 = {h2, h3};
            __nv_bfloat162 pl0 = {l0, l1}, pl1 = {l2, l3};
            hi[q * 2] = *(uint32_t*)&ph0; hi[q * 2 + 1] = *(uint32_t*)&ph1;
            lo[q * 2] = *(uint32_t*)&pl0; lo[q * 2 + 1] = *(uint32_t*)&pl1;
        }
        const uint32_t ah = sbase + buf * BUF_BYTES + OFF_AH + arow * ASTRIDE + ach * 2;
        const uint32_t al = sbase + buf * BUF_BYTES + OFF_AL + arow * ASTRIDE + ach * 2;
        asm volatile("st.shared.v4.b32 [%0], {%1,%2,%3,%4};" :: "r"(ah), "r"(hi[0]), "r"(hi[1]), "r"(hi[2]), "r"(hi[3]));
        asm volatile("st.shared.v4.b32 [%0], {%1,%2,%3,%4};" :: "r"(ah + 16), "r"(hi[4]), "r"(hi[5]), "r"(hi[6]), "r"(hi[7]));
        asm volatile("st.shared.v4.b32 [%0], {%1,%2,%3,%4};" :: "r"(al), "r"(lo[0]), "r"(lo[1]), "r"(lo[2]), "r"(lo[3]));
        asm volatile("st.shared.v4.b32 [%0], {%1,%2,%3,%4};" :: "r"(al + 16), "r"(lo[4]), "r"(lo[5]), "r"(lo[6]), "r"(lo[7]));
    };

    // ---- ldmatrix lane offsets (bytes) ----
    const uint32_t a_lane = (uint32_t)(((lane & 7) + ((lane >> 3) & 1) * 8) * ASTRIDE
                                       + (lane >> 4) * 16);
    const uint32_t b_lane = (uint32_t)(((lane & 7) + (lane >> 4) * 8) * ASTRIDE
                                       + ((lane >> 3) & 1) * 16);
    const uint32_t a_warp = (uint32_t)(warp_m * 64 * ASTRIDE);
    const uint32_t b_warp = (uint32_t)(warp_n * 64 * ASTRIDE);

    float acc[4][8][4] = {};   // [m-tile 16][n-tile 8][frag]

    // ---- prologue ----
    loadA(0);
    cpB(0, 0);
    __syncthreads();
    storeA(0, 0);
    CP_ASYNC_WAIT0();
    __syncthreads();

    // ---- main loop over 16 K-chunks ----
    for (int c = 0; c < 16; c++) {
        const int buf = c & 1;
        if (c < 15) { loadA(c + 1); cpB(c + 1, buf ^ 1); }

        const uint32_t bb = sbase + buf * BUF_BYTES;
        #pragma unroll
        for (int ks = 0; ks < 2; ks++) {
            // A fragments once per ks, shared by all 3 passes
            uint32_t ah[4][4], al[4][4];
            #pragma unroll
            for (int mt = 0; mt < 4; mt++) {
                ldsm_x4(ah[mt], bb + OFF_AH + a_warp + a_lane + mt * 16 * ASTRIDE + ks * 32);
                ldsm_x4(al[mt], bb + OFF_AL + a_warp + a_lane + mt * 16 * ASTRIDE + ks * 32);
            }
            #pragma unroll
            for (int g = 0; g < 4; g++) {
                uint32_t bh[4], bl[4];
                ldsm_x4(bh, bb + OFF_BH + b_warp + b_lane + g * 16 * ASTRIDE + ks * 32);
                #pragma unroll
                for (int mt = 0; mt < 4; mt++) {
                    mma_bf16(acc[mt][g * 2],     ah[mt], bh[0], bh[1]);
                    mma_bf16(acc[mt][g * 2 + 1], ah[mt], bh[2], bh[3]);
                    mma_bf16(acc[mt][g * 2],     al[mt], bh[0], bh[1]);
                    mma_bf16(acc[mt][g * 2 + 1], al[mt], bh[2], bh[3]);
                }
                ldsm_x4(bl, bb + OFF_BL + b_warp + b_lane + g * 16 * ASTRIDE + ks * 32);
                #pragma unroll
                for (int mt = 0; mt < 4; mt++) {
                    mma_bf16(acc[mt][g * 2],     ah[mt], bl[0], bl[1]);
                    mma_bf16(acc[mt][g * 2 + 1], ah[mt], bl[2], bl[3]);
                }
            }
        }

        if (c < 15) {
            storeA(c + 1, buf ^ 1);
            CP_ASYNC_WAIT0();
            __syncthreads();
        }
    }

    // ---- epilogue: bias + store ----
    const int colb = o0 + warp_n * 64 + (lane & 3) * 2;
    float2 bv[8];
    #pragma unroll
    for (int nj = 0; nj < 8; nj++)
        bv[nj] = __ldg((const float2*)&bo[colb + nj * 8]);

    const int rowb = j0 + warp_m * 64 + (lane >> 2);
    #pragma unroll
    for (int mt = 0; mt < 4; mt++) {
        #pragma unroll
        for (int h = 0; h < 2; h++) {
            const size_t rbase = ((size_t)i * NB + (rowb + mt * 16 + h * 8)) * OD;
            #pragma unroll
            for (int nj = 0; nj < 8; nj++) {
                float2 v;
                v.x = acc[mt][nj][h * 2]     + bv[nj].x;
                v.y = acc[mt][nj][h * 2 + 1] + bv[nj].y;
                *(float2*)&out[rbase + colb + nj * 8] = v;
            }
        }
    }
}

// ============================================================
// kernel_launch
// ============================================================
extern "C" void kernel_launch(void* const* d_in, const int* in_sizes, int n_in,
                              void* d_out, int out_size)
{
    const float* image = (const float*)d_in[0];
    const float* text  = (const float*)d_in[1];
    const float* Wx  = (const float*)d_in[3];
    const float* bx  = (const float*)d_in[4];
    const float* Wy  = (const float*)d_in[5];
    const float* by  = (const float*)d_in[6];
    const float* Wo  = (const float*)d_in[7];
    const float* bo  = (const float*)d_in[8];
    const float* Wa1 = (const float*)d_in[9];
    const float* ba1 = (const float*)d_in[10];
    const float* Wa2 = (const float*)d_in[11];
    const float* ba2 = (const float*)d_in[12];
    float* out = (float*)d_out;

    float *h, *logits, *textw, *outx, *gate, *tmp;
    __nv_bfloat16 *woth, *wotl;
    cudaGetSymbolAddress((void**)&h,      g_h);
    cudaGetSymbolAddress((void**)&logits, g_logits);
    cudaGetSymbolAddress((void**)&textw,  g_textw);
    cudaGetSymbolAddress((void**)&outx,   g_outx);
    cudaGetSymbolAddress((void**)&gate,   g_gate);
    cudaGetSymbolAddress((void**)&tmp,    g_tmp);
    cudaGetSymbolAddress((void**)&woth,   g_WoTh);
    cudaGetSymbolAddress((void**)&wotl,   g_WoTl);

    cudaFuncSetAttribute(big_einsum_hmma_kernel,
                         cudaFuncAttributeMaxDynamicSharedMemorySize, SMEM_BYTES);

    const dim3 gsm(OD / 32, NB / 64);   // (16, 8) = 128 CTAs

    // Wo transpose + bf16 hi/lo split
    split_transpose_wo<<<dim3(16, 16), dim3(32, 8)>>>(Wo, woth, wotl);
    // Stage 1 fused: h = relu(text@Wa1+ba1)  and  outx = image@Wx+bx
    pre_fused_kernel<<<dim3(OD / 32, NB / 64, 2), 128>>>(text, image, Wa1, ba1, Wx, bx, h, outx);
    // logits = h@Wa2+ba2
    gemm_small_kernel<0><<<gsm, 128>>>(h, Wa2, ba2, logits);
    // textw = softmax(logits) * text
    softmax_mul_kernel<<<NB, 512>>>(logits, text, textw);
    // gate = sigmoid(textw@Wy+by)
    gemm_small_kernel<2><<<gsm, 128>>>(textw, Wy, by, gate);

    if (out_size == NB * NB * OD) {
        dim3 grid(OD / 256, NB / 128, NB);   // (2, 4, 512)
        big_einsum_hmma_kernel<<<grid, 256, SMEM_BYTES>>>(outx, gate, bo, out);
    } else {
        mul_kernel<<<(NB * DD + 255) / 256, 256>>>(gate, outx, tmp, NB * DD);
        gemm_small_kernel<0><<<gsm, 128>>>(tmp, Wo, bo, out);
    }
}

// round 5
// speedup vs baseline: 4.4434x; 2.0714x over previous
#include <cuda_runtime.h>
#include <cuda_fp16.h>
#include <cstdint>

#define NB 512   // batch
#define DD 512   // embed dim
#define OD 512   // out dim

// -------- scratch (no cudaMalloc allowed) --------
__device__ float g_h[NB * DD];
__device__ float g_logits[NB * DD];
__device__ float g_textw[NB * DD];
__device__ float g_outx[NB * DD];
__device__ float g_gate[NB * DD];
__device__ float g_tmp[NB * DD];
__device__ __half g_WoT[OD * DD];   // WoT[o][d] = fp16(Wo[d][o])

// ============================================================
// Helpers (plain sm_80+ PTX: mma.sync / ldmatrix / cp.async)
// ============================================================
__device__ __forceinline__ uint32_t smem_u32(const void* p) {
    uint32_t a;
    asm("{ .reg .u64 t; cvta.to.shared.u64 t, %1; cvt.u32.u64 %0, t; }"
        : "=r"(a) : "l"(p));
    return a;
}

#define CP_ASYNC_16(dst, src) \
    asm volatile("cp.async.cg.shared.global [%0], [%1], 16;" \
                 :: "r"((uint32_t)(dst)), "l"(src))
#define CP_ASYNC_COMMIT() asm volatile("cp.async.commit_group;" ::: "memory")
#define CP_ASYNC_WAIT0()  asm volatile("cp.async.wait_group 0;" ::: "memory")

__device__ __forceinline__ void ldsm_x4(uint32_t r[4], uint32_t addr) {
    asm volatile("ldmatrix.sync.aligned.m8n8.x4.shared.b16 {%0,%1,%2,%3}, [%4];"
                 : "=r"(r[0]), "=r"(r[1]), "=r"(r[2]), "=r"(r[3]) : "r"(addr));
}

__device__ __forceinline__ void mma_fp16(float c[4], const uint32_t a[4],
                                         const uint32_t b0, const uint32_t b1) {
    asm volatile(
        "mma.sync.aligned.m16n8k16.row.col.f32.f16.f16.f32 "
        "{%0,%1,%2,%3}, {%4,%5,%6,%7}, {%8,%9}, {%0,%1,%2,%3};"
        : "+f"(c[0]), "+f"(c[1]), "+f"(c[2]), "+f"(c[3])
        : "r"(a[0]), "r"(a[1]), "r"(a[2]), "r"(a[3]), "r"(b0), "r"(b1));
}

// ============================================================
// smem layout for big kernel (dynamic)
//   gate row: 2048 B
//   2 buffers, each: A(128x80=10240) B(256x80=20480) = 30720 B
//   rows: 32 fp16 (64B) data + 16B pad, stride 80 (ldmatrix conflict-free)
// ============================================================
#define ASTRIDE 80
#define OFF_A 0
#define OFF_B 10240
#define BUF_BYTES 30720
#define SMEM_BYTES (2048 + 2 * BUF_BYTES)   // 63488

// ============================================================
// Preamble small GEMM core: BM=64, BN=32, BK=16, 128 threads
// ============================================================
template <int ACT>
__device__ __forceinline__ void gemm_small_body(
    const float* __restrict__ A, const float* __restrict__ W,
    const float* __restrict__ bias, float* __restrict__ C,
    int m0, int n0)
{
    __shared__ float As[16][64];
    __shared__ float Bs[16][32];
    const int t = threadIdx.x;
    const int tx = t & 7, ty = t >> 3;
    float acc[4][4] = {};
    for (int k0 = 0; k0 < DD; k0 += 16) {
        {
            const int m = t >> 1;
            const int kq = (t & 1) * 8;
            float4 v0 = *(const float4*)&A[(size_t)(m0 + m) * DD + k0 + kq];
            float4 v1 = *(const float4*)&A[(size_t)(m0 + m) * DD + k0 + kq + 4];
            As[kq + 0][m] = v0.x; As[kq + 1][m] = v0.y;
            As[kq + 2][m] = v0.z; As[kq + 3][m] = v0.w;
            As[kq + 4][m] = v1.x; As[kq + 5][m] = v1.y;
            As[kq + 6][m] = v1.z; As[kq + 7][m] = v1.w;
        }
        {
            const int k = t >> 3, n = (t & 7) * 4;
            *(float4*)&Bs[k][n] = *(const float4*)&W[(size_t)(k0 + k) * OD + n0 + n];
        }
        __syncthreads();
        #pragma unroll
        for (int k = 0; k < 16; k++) {
            float a[4], b[4];
            *(float4*)a = *(const float4*)&As[k][ty * 4];
            *(float4*)b = *(const float4*)&Bs[k][tx * 4];
            #pragma unroll
            for (int r = 0; r < 4; r++)
                #pragma unroll
                for (int c = 0; c < 4; c++)
                    acc[r][c] += a[r] * b[c];
        }
        __syncthreads();
    }
    #pragma unroll
    for (int r = 0; r < 4; r++) {
        const int m = m0 + ty * 4 + r;
        float4 v; float* vv = (float*)&v;
        #pragma unroll
        for (int c = 0; c < 4; c++) {
            float x = acc[r][c] + __ldg(&bias[n0 + tx * 4 + c]);
            if (ACT == 1) x = fmaxf(x, 0.0f);
            if (ACT == 2) x = 1.0f / (1.0f + __expf(-x));
            vv[c] = x;
        }
        *(float4*)&C[(size_t)m * OD + n0 + tx * 4] = v;
    }
}

template <int ACT>
__global__ void __launch_bounds__(128)
gemm_small_kernel(const float* __restrict__ A, const float* __restrict__ W,
                  const float* __restrict__ bias, float* __restrict__ C)
{
    gemm_small_body<ACT>(A, W, bias, C, blockIdx.y * 64, blockIdx.x * 32);
}

// Fused first stage: z=0 -> h = relu(text@Wa1+ba1); z=1 -> outx = image@Wx+bx
__global__ void __launch_bounds__(128)
pre_fused_kernel(const float* __restrict__ text, const float* __restrict__ image,
                 const float* __restrict__ Wa1, const float* __restrict__ ba1,
                 const float* __restrict__ Wx,  const float* __restrict__ bx,
                 float* __restrict__ h, float* __restrict__ outx)
{
    if (blockIdx.z == 0)
        gemm_small_body<1>(text, Wa1, ba1, h, blockIdx.y * 64, blockIdx.x * 32);
    else
        gemm_small_body<0>(image, Wx, bx, outx, blockIdx.y * 64, blockIdx.x * 32);
}

// ============================================================
// Preamble: row softmax * text
// ============================================================
__global__ void __launch_bounds__(512)
softmax_mul_kernel(const float* __restrict__ logits, const float* __restrict__ text,
                   float* __restrict__ out)
{
    __shared__ float sdata[512];
    const int row = blockIdx.x, t = threadIdx.x;
    const float v = logits[(size_t)row * DD + t];
    sdata[t] = v; __syncthreads();
    for (int s = 256; s > 0; s >>= 1) { if (t < s) sdata[t] = fmaxf(sdata[t], sdata[t + s]); __syncthreads(); }
    const float mx = sdata[0]; __syncthreads();
    const float e = __expf(v - mx);
    sdata[t] = e; __syncthreads();
    for (int s = 256; s > 0; s >>= 1) { if (t < s) sdata[t] += sdata[t + s]; __syncthreads(); }
    out[(size_t)row * DD + t] = e * (1.0f / sdata[0]) * text[(size_t)row * DD + t];
}

// ============================================================
// Preamble: transpose Wo -> fp16:  WoT[o][d] = fp16(Wo[d][o])
// ============================================================
__global__ void __launch_bounds__(256)
transpose_wo_h(const float* __restrict__ Wo, __half* __restrict__ T)
{
    __shared__ float tile[32][33];
    const int bo = blockIdx.x * 32;
    const int bd = blockIdx.y * 32;
    const int x = threadIdx.x, y = threadIdx.y;   // (32, 8)
    #pragma unroll
    for (int r = 0; r < 4; r++)
        tile[y + 8 * r][x] = Wo[(size_t)(bd + y + 8 * r) * OD + bo + x];
    __syncthreads();
    #pragma unroll
    for (int r = 0; r < 4; r++) {
        const int o = bo + y + 8 * r;
        const int d = bd + x;
        T[(size_t)o * DD + d] = __float2half_rn(tile[x][y + 8 * r]);
    }
}

__global__ void mul_kernel(const float* __restrict__ a, const float* __restrict__ b,
                           float* __restrict__ c, int n)
{
    int idx = blockIdx.x * blockDim.x + threadIdx.x;
    if (idx < n) c[idx] = a[idx] * b[idx];
}

// ============================================================
// Big einsum via single-pass fp16 HMMA:
//   out[i,j,o] = sum_d gate[i,d]*outx[j,d]*Wo[d,o] + bo[o]
// grid (2 o-tiles, 4 j-tiles, 512 i) = 4096 CTAs, 512 threads (16 warps).
// CTA tile 128(j) x 256(o); warp tile 32x64 (warp_m = wid&3, warp_n = wid>>2).
// K chunks of 32, double-buffered cp.async B + register-staged A.
// ============================================================
__global__ void __launch_bounds__(512, 1)
big_einsum_hmma_kernel(const float* __restrict__ outx, const float* __restrict__ gate,
                       const float* __restrict__ bo, float* __restrict__ out)
{
    extern __shared__ char dynsmem[];
    float* gs = (float*)dynsmem;
    const uint32_t sbase = smem_u32(dynsmem) + 2048u;

    const int i  = blockIdx.z;
    const int j0 = blockIdx.y * 128;
    const int o0 = blockIdx.x * 256;
    const int tid  = threadIdx.x;
    const int wid  = tid >> 5;
    const int lane = tid & 31;
    const int warp_m = wid & 3;     // 4 x 32 rows (j)
    const int warp_n = wid >> 2;    // 4 x 64 cols (o)

    // ---- gate row -> smem ----
    gs[tid] = gate[(size_t)i * DD + tid];

    // ---- A-build indices: row = tid>>2 (0..127), 8-col group ----
    const int arow = tid >> 2;
    const int ach  = (tid & 3) * 8;

    // ---- cp.async B: 256 rows x 64B per chunk ----
    auto cpB = [&](int c, int buf) {
        const int c0 = c * 32;
        const uint32_t bdst = sbase + buf * BUF_BYTES + OFF_B;
        #pragma unroll
        for (int q = 0; q < 2; q++) {
            const int g   = tid + q * 512;      // 0..1023
            const int row = g >> 2;             // 0..255
            const int ck  = g & 3;
            const uint32_t dso = (uint32_t)(row * ASTRIDE + ck * 16);
            const __half* src = g_WoT + (size_t)(o0 + row) * DD + c0 + ck * 8;
            CP_ASYNC_16(bdst + dso, src);
        }
        CP_ASYNC_COMMIT();
    };

    // ---- A gmem load (registers) ----
    float4 av[2];
    auto loadA = [&](int c) {
        const float* p = outx + (size_t)(j0 + arow) * DD + c * 32 + ach;
        av[0] = __ldg((const float4*)p);
        av[1] = __ldg((const float4*)(p + 4));
    };

    // ---- A convert (gate-scaled) + fp16 store ----
    auto storeA = [&](int c, int buf) {
        const int d0 = c * 32 + ach;
        const float4 ga = *(const float4*)&gs[d0];
        const float4 gb = *(const float4*)&gs[d0 + 4];
        __half2 h0 = __float22half2_rn(make_float2(av[0].x * ga.x, av[0].y * ga.y));
        __half2 h1 = __float22half2_rn(make_float2(av[0].z * ga.z, av[0].w * ga.w));
        __half2 h2 = __float22half2_rn(make_float2(av[1].x * gb.x, av[1].y * gb.y));
        __half2 h3 = __float22half2_rn(make_float2(av[1].z * gb.z, av[1].w * gb.w));
        const uint32_t ad = sbase + buf * BUF_BYTES + OFF_A + arow * ASTRIDE + ach * 2;
        asm volatile("st.shared.v4.b32 [%0], {%1,%2,%3,%4};"
                     :: "r"(ad), "r"(*(uint32_t*)&h0), "r"(*(uint32_t*)&h1),
                        "r"(*(uint32_t*)&h2), "r"(*(uint32_t*)&h3));
    };

    // ---- ldmatrix lane offsets (bytes) ----
    const uint32_t a_lane = (uint32_t)(((lane & 7) + ((lane >> 3) & 1) * 8) * ASTRIDE
                                       + (lane >> 4) * 16);
    const uint32_t b_lane = (uint32_t)(((lane & 7) + (lane >> 4) * 8) * ASTRIDE
                                       + ((lane >> 3) & 1) * 16);
    const uint32_t a_warp = (uint32_t)(warp_m * 32 * ASTRIDE);
    const uint32_t b_warp = (uint32_t)(warp_n * 64 * ASTRIDE);

    float acc[2][8][4] = {};   // [m-tile 16][n-group 8][frag]

    // ---- prologue ----
    loadA(0);
    cpB(0, 0);
    __syncthreads();          // gs visible
    storeA(0, 0);
    CP_ASYNC_WAIT0();
    __syncthreads();          // buffer 0 ready

    // ---- main loop over 16 K-chunks ----
    for (int c = 0; c < 16; c++) {
        const int buf = c & 1;
        if (c < 15) { loadA(c + 1); cpB(c + 1, buf ^ 1); }

        const uint32_t bb = sbase + buf * BUF_BYTES;
        #pragma unroll
        for (int ks = 0; ks < 2; ks++) {
            uint32_t ah[2][4];
            ldsm_x4(ah[0], bb + OFF_A + a_warp + a_lane + ks * 32);
            ldsm_x4(ah[1], bb + OFF_A + a_warp + a_lane + 16 * ASTRIDE + ks * 32);
            #pragma unroll
            for (int g = 0; g < 4; g++) {
                uint32_t bh[4];
                ldsm_x4(bh, bb + OFF_B + b_warp + b_lane + g * 16 * ASTRIDE + ks * 32);
                mma_fp16(acc[0][g * 2],     ah[0], bh[0], bh[1]);
                mma_fp16(acc[0][g * 2 + 1], ah[0], bh[2], bh[3]);
                mma_fp16(acc[1][g * 2],     ah[1], bh[0], bh[1]);
                mma_fp16(acc[1][g * 2 + 1], ah[1], bh[2], bh[3]);
            }
        }

        if (c < 15) {
            storeA(c + 1, buf ^ 1);
            CP_ASYNC_WAIT0();
            __syncthreads();
        }
    }

    // ---- epilogue: bias + store ----
    const int colb = o0 + warp_n * 64 + (lane & 3) * 2;
    float2 bv[8];
    #pragma unroll
    for (int nj = 0; nj < 8; nj++)
        bv[nj] = __ldg((const float2*)&bo[colb + nj * 8]);

    const int rowb = j0 + warp_m * 32 + (lane >> 2);
    #pragma unroll
    for (int mt = 0; mt < 2; mt++) {
        #pragma unroll
        for (int h = 0; h < 2; h++) {
            const size_t rbase = ((size_t)i * NB + (rowb + mt * 16 + h * 8)) * OD;
            #pragma unroll
            for (int nj = 0; nj < 8; nj++) {
                float2 v;
                v.x = acc[mt][nj][h * 2]     + bv[nj].x;
                v.y = acc[mt][nj][h * 2 + 1] + bv[nj].y;
                *(float2*)&out[rbase + colb + nj * 8] = v;
            }
        }
    }
}

// ============================================================
// kernel_launch
// ============================================================
extern "C" void kernel_launch(void* const* d_in, const int* in_sizes, int n_in,
                              void* d_out, int out_size)
{
    const float* image = (const float*)d_in[0];
    const float* text  = (const float*)d_in[1];
    const float* Wx  = (const float*)d_in[3];
    const float* bx  = (const float*)d_in[4];
    const float* Wy  = (const float*)d_in[5];
    const float* by  = (const float*)d_in[6];
    const float* Wo  = (const float*)d_in[7];
    const float* bo  = (const float*)d_in[8];
    const float* Wa1 = (const float*)d_in[9];
    const float* ba1 = (const float*)d_in[10];
    const float* Wa2 = (const float*)d_in[11];
    const float* ba2 = (const float*)d_in[12];
    float* out = (float*)d_out;

    float *h, *logits, *textw, *outx, *gate, *tmp;
    __half* wot;
    cudaGetSymbolAddress((void**)&h,      g_h);
    cudaGetSymbolAddress((void**)&logits, g_logits);
    cudaGetSymbolAddress((void**)&textw,  g_textw);
    cudaGetSymbolAddress((void**)&outx,   g_outx);
    cudaGetSymbolAddress((void**)&gate,   g_gate);
    cudaGetSymbolAddress((void**)&tmp,    g_tmp);
    cudaGetSymbolAddress((void**)&wot,    g_WoT);

    cudaFuncSetAttribute(big_einsum_hmma_kernel,
                         cudaFuncAttributeMaxDynamicSharedMemorySize, SMEM_BYTES);

    const dim3 gsm(OD / 32, NB / 64);   // (16, 8) = 128 CTAs

    // Wo transpose -> fp16
    transpose_wo_h<<<dim3(16, 16), dim3(32, 8)>>>(Wo, wot);
    // Stage 1 fused: h = relu(text@Wa1+ba1)  and  outx = image@Wx+bx
    pre_fused_kernel<<<dim3(OD / 32, NB / 64, 2), 128>>>(text, image, Wa1, ba1, Wx, bx, h, outx);
    // logits = h@Wa2+ba2
    gemm_small_kernel<0><<<gsm, 128>>>(h, Wa2, ba2, logits);
    // textw = softmax(logits) * text
    softmax_mul_kernel<<<NB, 512>>>(logits, text, textw);
    // gate = sigmoid(textw@Wy+by)
    gemm_small_kernel<2><<<gsm, 128>>>(textw, Wy, by, gate);

    if (out_size == NB * NB * OD) {
        dim3 grid(OD / 256, NB / 128, NB);   // (2, 4, 512)
        big_einsum_hmma_kernel<<<grid, 512, SMEM_BYTES>>>(outx, gate, bo, out);
    } else {
        mul_kernel<<<(NB * DD + 255) / 256, 256>>>(gate, outx, tmp, NB * DD);
        gemm_small_kernel<0><<<gsm, 128>>>(tmp, Wo, bo, out);
    }
}